// round 4
// baseline (speedup 1.0000x reference)
#include <cuda_runtime.h>
#include <cuda_bf16.h>
#include <math.h>
#include <stdint.h>

// ---------------- problem constants ----------------
#define B_SZ 8
#define P_SZ 4096
#define NPATH (B_SZ * P_SZ)      // 32768
#define S_SZ 16
#define NFIB 128
#define NBAND 10
#define FLEN 1023
#define RIRLEN 96000
#define EPS 1e-9f

// ---------------- device scratch ----------------
__device__ float g_cosW[512 * 512];     // cos(2*pi*k*n/1023) (symmetric)
__device__ float g_sinW[512 * 512];     // sin(2*pi*k*n/1023) (symmetric)
__device__ float g_T[20 * 512];
__device__ float g_G[20 * 512];
__device__ float g_logrefl[S_SZ * NBAND];
__device__ float g_sigdir[NFIB * NBAND];
__device__ __nv_bfloat16 g_ch[512 * 512], g_cl[512 * 512];
__device__ __nv_bfloat16 g_sh[512 * 512], g_sl[512 * 512];
__device__ __nv_bfloat16 g_reh[NPATH * 512], g_rel[NPATH * 512];
__device__ __nv_bfloat16 g_imh[NPATH * 512], g_iml[NPATH * 512];
__device__ float g_rir[B_SZ * RIRLEN];

// ---------------- launch 1: zero RIR + tiny param transforms ----------------
__global__ void init_kernel(const float* __restrict__ sp,
                            const float* __restrict__ dp) {
    int i = blockIdx.x * blockDim.x + threadIdx.x;
    if (i < B_SZ * RIRLEN) g_rir[i] = 0.f;
    if (i < S_SZ * NBAND) {
        float s = 1.f / (1.f + expf(-sp[i]));
        g_logrefl[i] = logf(s <= EPS ? EPS : s);
    }
    if (i < NFIB * NBAND) {
        g_sigdir[i] = 1.f / (1.f + expf(-dp[i]));
    }
}

// ---------------- launch 2: twiddles (fp32 + bf16 hi/lo split) ----------------
__global__ void pre_twiddle_kernel() {
    int i = blockIdx.x * blockDim.x + threadIdx.x;
    if (i >= 512 * 512) return;
    int k = i >> 9, n = i & 511;
    int m = (k * n) % FLEN;                 // exact
    float x = (float)m * (2.0f / 1023.0f);  // in [0,2)
    float s, c;
    sincospif(x, &s, &c);
    g_cosW[i] = c;
    g_sinW[i] = s;
    __nv_bfloat16 ch = __float2bfloat16(c);
    g_ch[i] = ch; g_cl[i] = __float2bfloat16(c - __bfloat162float(ch));
    __nv_bfloat16 sh = __float2bfloat16(s);
    g_sh[i] = sh; g_sl[i] = __float2bfloat16(s - __bfloat162float(sh));
}

// ---------------- launch 3: T[j][n] ----------------
__global__ void pre_T_kernel(const float* __restrict__ si,
                             const float* __restrict__ di) {
    int gw = (blockIdx.x * 256 + threadIdx.x) >> 5;
    int lane = threadIdx.x & 31;
    if (gw >= 20 * 512) return;
    int j = gw >> 9, n = gw & 511;
    const float* row = (j < 10) ? (si + j * 512) : (di + (j - 10) * 512);
    float acc = 0.f;
    for (int k = 1 + lane; k < 512; k += 32)
        acc += row[k] * g_cosW[n * 512 + k];
    acc *= 2.f;
#pragma unroll
    for (int o = 16; o; o >>= 1) acc += __shfl_xor_sync(0xffffffffu, acc, o);
    if (lane == 0) g_T[gw] = acc + row[0];
}

// ---------------- launch 4: G[j][q] ----------------
__global__ void pre_G_kernel() {
    int gw = (blockIdx.x * 256 + threadIdx.x) >> 5;
    int lane = threadIdx.x & 31;
    if (gw >= 20 * 512) return;
    int j = gw >> 9, q = gw & 511;
    float acc = 0.f;
    for (int n = 1 + lane; n < 512; n += 32)
        acc += g_T[j * 512 + n] * g_sinW[q * 512 + n];
#pragma unroll
    for (int o = 16; o; o >>= 1) acc += __shfl_xor_sync(0xffffffffu, acc, o);
    if (lane == 0) g_G[gw] = acc * (-2.f / (float)FLEN);
}

// ---------------- launch 5: per-path spectrum (warp per path) ----------------
__global__ void __launch_bounds__(128) fr_kernel(
    const float* __restrict__ path_dirs,
    const float* __restrict__ surf_interp,
    const float* __restrict__ dir_interp,
    const float* __restrict__ fib,
    const int* __restrict__ mask,
    const int* __restrict__ delays) {
    int wid = threadIdx.x >> 5, lane = threadIdx.x & 31;
    int path = blockIdx.x * 4 + wid;

    __shared__ float sh_c[4][20];

    // surface coefficients (lanes 0..9)
    if (lane < NBAND) {
        const int* m = mask + path * S_SZ;
        float acc = 0.f;
#pragma unroll
        for (int s = 0; s < S_SZ; s++) acc += (float)m[s] * g_logrefl[s * NBAND + lane];
        sh_c[wid][lane] = acc;
    }

    // normalized direction
    float dx = path_dirs[path * 3 + 0];
    float dy = path_dirs[path * 3 + 1];
    float dz = path_dirs[path * 3 + 2];
    float inv = 1.f / (sqrtf(dx * dx + dy * dy + dz * dz) + EPS);
    dx *= inv; dy *= inv; dz *= inv;

    // 4 logits per lane over 128 fib points
    float lg[4];
    float mx = -1e30f;
#pragma unroll
    for (int j = 0; j < 4; j++) {
        int n = j * 32 + lane;
        lg[j] = 8.f * (dx * fib[n * 3 + 0] + dy * fib[n * 3 + 1] + dz * fib[n * 3 + 2]);
        mx = fmaxf(mx, lg[j]);
    }
#pragma unroll
    for (int o = 16; o; o >>= 1) mx = fmaxf(mx, __shfl_xor_sync(0xffffffffu, mx, o));
    float ev[4];
    float tot = 0.f;
#pragma unroll
    for (int j = 0; j < 4; j++) { ev[j] = __expf(lg[j] - mx); tot += ev[j]; }
#pragma unroll
    for (int o = 16; o; o >>= 1) tot += __shfl_xor_sync(0xffffffffu, tot, o);
    float itot = 1.f / tot;

    // directivity: amp[band] = (sum_n e_n * sigdir[n][band]) / tot
#pragma unroll
    for (int band = 0; band < NBAND; band++) {
        float p = 0.f;
#pragma unroll
        for (int j = 0; j < 4; j++)
            p += ev[j] * g_sigdir[(j * 32 + lane) * NBAND + band];
#pragma unroll
        for (int o = 16; o; o >>= 1) p += __shfl_xor_sync(0xffffffffu, p, o);
        if (lane == 0) {
            float amp = p * itot;
            sh_c[wid][10 + band] = logf(amp <= EPS ? EPS : amp);
        }
    }
    __syncwarp();

    int dly = delays[path];
    float gain = 1.f / fmaxf((float)dly * (1.f / 48.f), 1.f);
    float base_scale = gain * (1.f / (float)FLEN);

    float c[20];
#pragma unroll
    for (int j = 0; j < 20; j++) c[j] = sh_c[wid][j];

#pragma unroll 2
    for (int q = lane; q < 512; q += 32) {
        float la = 0.f, ph = 0.f;
#pragma unroll
        for (int j = 0; j < 10; j++) la += c[j] * surf_interp[j * 512 + q];
#pragma unroll
        for (int j = 0; j < 10; j++) la += c[10 + j] * dir_interp[j * 512 + q];
#pragma unroll
        for (int j = 0; j < 20; j++) ph += c[j] * g_G[j * 512 + q];
        float a = __expf(la) * base_scale * (q == 0 ? 1.f : 2.f);
        float kk = rintf(ph * 0.15915494309189535f);
        float phr = fmaf(-6.2831855f, kk, ph);
        phr = fmaf(1.7484555e-7f, kk, phr);
        float sn, cs;
        __sincosf(phr, &sn, &cs);
        float vr = a * cs;
        float vi = -a * sn;
        size_t o = (size_t)path * 512 + q;
        __nv_bfloat16 rh = __float2bfloat16(vr);
        g_reh[o] = rh; g_rel[o] = __float2bfloat16(vr - __bfloat162float(rh));
        __nv_bfloat16 ih = __float2bfloat16(vi);
        g_imh[o] = ih; g_iml[o] = __float2bfloat16(vi - __bfloat162float(ih));
    }
}

// ---------------- launch 6: tensor-core DFT + fused scatter ----------------
#define GST 24  // smem row stride in bf16 (16 data + 8 pad) -> 48B, 16B aligned
#define STAGE_ELEMS (8 * 128 * GST)   // bf16 elems per stage (49152 B)

#define LDSM4(r, addr)                                                      \
    asm volatile("ldmatrix.sync.aligned.m8n8.x4.shared.b16 {%0,%1,%2,%3}, [%4];" \
                 : "=r"((r)[0]), "=r"((r)[1]), "=r"((r)[2]), "=r"((r)[3])   \
                 : "r"(addr))

#define MMA_BF16(acc, a, b0, b1)                                            \
    asm volatile("mma.sync.aligned.m16n8k16.row.col.f32.bf16.bf16.f32 "     \
                 "{%0,%1,%2,%3}, {%4,%5,%6,%7}, {%8,%9}, {%0,%1,%2,%3};"    \
                 : "+f"((acc)[0]), "+f"((acc)[1]), "+f"((acc)[2]), "+f"((acc)[3]) \
                 : "r"((a)[0]), "r"((a)[1]), "r"((a)[2]), "r"((a)[3]),      \
                   "r"(b0), "r"(b1))

__device__ __forceinline__ void cp16(unsigned saddr, const void* gaddr) {
    asm volatile("cp.async.ca.shared.global [%0], [%1], 16;\n"
                 :: "r"(saddr), "l"(gaddr));
}

extern __shared__ __nv_bfloat16 dynsm[];

__global__ void __launch_bounds__(256, 1) gemm_scatter_kernel(
    const int* __restrict__ delays) {
    // tiles per stage: 0 reh, 1 rel, 2 imh, 3 iml, 4 ch, 5 cl, 6 sh, 7 sl
    int tid = threadIdx.x;
    int wid = tid >> 5, lane = tid & 31;
    int wm = (wid & 3) * 32;
    int wn = (wid >> 2) * 64;
    int rowBase = blockIdx.y * 128;
    int colBase = blockIdx.x * 128;

    const __nv_bfloat16* gsrc[8] = {g_reh, g_rel, g_imh, g_iml, g_ch, g_cl, g_sh, g_sl};
    int lr = tid >> 1;            // row 0..127
    int lc = (tid & 1) * 8;       // elem offset (8 bf16 = 16B)

    float accC[2][8][4];
    float accS[2][8][4];
#pragma unroll
    for (int mt = 0; mt < 2; mt++)
#pragma unroll
        for (int nt = 0; nt < 8; nt++)
#pragma unroll
            for (int r = 0; r < 4; r++) { accC[mt][nt][r] = 0.f; accS[mt][nt][r] = 0.f; }

    unsigned smbase = (unsigned)__cvta_generic_to_shared(dynsm);
    int sel = lane >> 3, fr8 = lane & 7;
    int a_row_off = ((sel & 1) << 3) + fr8;
    int a_koff = (sel >> 1) << 3;
    int b_row_off = ((sel >> 1) << 3) + fr8;
    int b_koff = (sel & 1) << 3;

    // per-thread cp.async source rows (same for every k-step)
    size_t goff[8];
#pragma unroll
    for (int t = 0; t < 8; t++) {
        int gr = (t < 4 ? rowBase : colBase) + lr;
        goff[t] = (size_t)gr * 512 + lc;
    }
    unsigned sdst = smbase + (unsigned)(((0 * 128 + lr) * GST + lc) * 2);

    // prologue: stage 0 <- k0 = 0
#pragma unroll
    for (int t = 0; t < 8; t++)
        cp16(smbase + (unsigned)(((t * 128 + lr) * GST + lc) * 2),
             gsrc[t] + goff[t]);
    asm volatile("cp.async.commit_group;\n");

    int buf = 0;
    for (int k0 = 0; k0 < 512; k0 += 16) {
        if (k0 + 16 < 512) {
            unsigned sb = smbase + (unsigned)((buf ^ 1) * STAGE_ELEMS * 2);
#pragma unroll
            for (int t = 0; t < 8; t++)
                cp16(sb + (unsigned)(((t * 128 + lr) * GST + lc) * 2),
                     gsrc[t] + goff[t] + (k0 + 16));
            asm volatile("cp.async.commit_group;\n");
            asm volatile("cp.async.wait_group 1;\n");
        } else {
            asm volatile("cp.async.wait_group 0;\n");
        }
        __syncthreads();

        unsigned sbase = smbase + (unsigned)(buf * STAGE_ELEMS * 2);
        uint32_t af[4][2][4];
#pragma unroll
        for (int mat = 0; mat < 4; mat++)
#pragma unroll
            for (int mt = 0; mt < 2; mt++) {
                int row = wm + mt * 16 + a_row_off;
                unsigned addr = sbase + ((mat * 128 + row) * GST + a_koff) * 2;
                LDSM4(af[mat][mt], addr);
            }
#pragma unroll
        for (int g = 0; g < 4; g++) {
            uint32_t bf[4][4];
#pragma unroll
            for (int mat = 0; mat < 4; mat++) {
                int row = wn + g * 16 + b_row_off;
                unsigned addr = sbase + (((4 + mat) * 128 + row) * GST + b_koff) * 2;
                LDSM4(bf[mat], addr);
            }
#pragma unroll
            for (int mt = 0; mt < 2; mt++) {
#pragma unroll
                for (int j = 0; j < 2; j++) {
                    int nt = g * 2 + j;
                    MMA_BF16(accC[mt][nt], af[0][mt], bf[0][2 * j], bf[0][2 * j + 1]); // reh*ch
                    MMA_BF16(accC[mt][nt], af[0][mt], bf[1][2 * j], bf[1][2 * j + 1]); // reh*cl
                    MMA_BF16(accC[mt][nt], af[1][mt], bf[0][2 * j], bf[0][2 * j + 1]); // rel*ch
                    MMA_BF16(accS[mt][nt], af[2][mt], bf[2][2 * j], bf[2][2 * j + 1]); // imh*sh
                    MMA_BF16(accS[mt][nt], af[2][mt], bf[3][2 * j], bf[3][2 * j + 1]); // imh*sl
                    MMA_BF16(accS[mt][nt], af[3][mt], bf[2][2 * j], bf[2][2 * j + 1]); // iml*sh
                }
            }
        }
        __syncthreads();
        buf ^= 1;
    }

    // epilogue: scatter into RIR with atomics
    int r0 = lane >> 2, cp = (lane & 3) * 2;
#pragma unroll
    for (int mt = 0; mt < 2; mt++) {
#pragma unroll
        for (int half = 0; half < 2; half++) {
            int path = rowBase + wm + mt * 16 + half * 8 + r0;
            int dly = delays[path];
            float* rir = g_rir + (size_t)(path >> 12) * RIRLEN + dly;
#pragma unroll
            for (int nt = 0; nt < 8; nt++) {
                int n = colBase + wn + nt * 8 + cp;
                float c0 = accC[mt][nt][half * 2 + 0], s0 = accS[mt][nt][half * 2 + 0];
                float c1 = accC[mt][nt][half * 2 + 1], s1 = accS[mt][nt][half * 2 + 1];
                atomicAdd(rir + n, c0 - s0);
                atomicAdd(rir + n + 1, c1 - s1);
                if (n > 0) atomicAdd(rir + FLEN - n, c0 + s0);
                atomicAdd(rir + FLEN - (n + 1), c1 + s1);
            }
        }
    }
}

// ---------------- launch 7: 'same' cross-correlation ----------------
#define CT 1024
__global__ void __launch_bounds__(256) conv_kernel(const float* __restrict__ sk,
                                                   float* __restrict__ out) {
    __shared__ float s_rir[CT + 1024];
    __shared__ float s_k[1024];
    int b = blockIdx.y;
    int t0 = blockIdx.x * CT;
    int tid = threadIdx.x;

    for (int i = tid; i < CT + 1024; i += 256) {
        int idx = t0 - 511 + i;
        s_rir[i] = (idx >= 0 && idx < RIRLEN) ? g_rir[(size_t)b * RIRLEN + idx] : 0.f;
    }
    for (int i = tid; i < 1024; i += 256) s_k[i] = (i < FLEN) ? sk[i] : 0.f;
    __syncthreads();

    int base = tid * 4;
    float4 acc = make_float4(0.f, 0.f, 0.f, 0.f);
#pragma unroll 4
    for (int l = 0; l < 1024; l += 4) {
        float4 kv = *(const float4*)&s_k[l];
        float4 f0 = *(const float4*)&s_rir[base + l];
        float4 f1 = *(const float4*)&s_rir[base + l + 4];
        acc.x += kv.x * f0.x + kv.y * f0.y + kv.z * f0.z + kv.w * f0.w;
        acc.y += kv.x * f0.y + kv.y * f0.z + kv.z * f0.w + kv.w * f1.x;
        acc.z += kv.x * f0.z + kv.y * f0.w + kv.z * f1.x + kv.w * f1.y;
        acc.w += kv.x * f0.w + kv.y * f1.x + kv.z * f1.y + kv.w * f1.z;
    }
    int tbase = t0 + base;
    if (tbase + 0 < RIRLEN) out[(size_t)b * RIRLEN + tbase + 0] = acc.x;
    if (tbase + 1 < RIRLEN) out[(size_t)b * RIRLEN + tbase + 1] = acc.y;
    if (tbase + 2 < RIRLEN) out[(size_t)b * RIRLEN + tbase + 2] = acc.z;
    if (tbase + 3 < RIRLEN) out[(size_t)b * RIRLEN + tbase + 3] = acc.w;
}

// ---------------- launch ----------------
extern "C" void kernel_launch(void* const* d_in, const int* in_sizes, int n_in,
                              void* d_out, int out_size) {
    const float* surface_params = (const float*)d_in[0];
    const float* dir_params     = (const float*)d_in[1];
    const float* path_dirs      = (const float*)d_in[2];
    const float* source_kernel  = (const float*)d_in[3];
    const float* surf_interp    = (const float*)d_in[4];
    const float* dir_interp     = (const float*)d_in[5];
    const float* fib_points     = (const float*)d_in[6];
    const int*   mask           = (const int*)d_in[7];
    const int*   delays         = (const int*)d_in[8];
    float* out = (float*)d_out;

    static int smem_set = 0;
    if (!smem_set) {
        cudaFuncSetAttribute(gemm_scatter_kernel,
                             cudaFuncAttributeMaxDynamicSharedMemorySize,
                             2 * STAGE_ELEMS * 2);
        smem_set = 1;
    }

    init_kernel<<<(B_SZ * RIRLEN + 1023) / 1024, 1024>>>(surface_params, dir_params); // 1
    pre_twiddle_kernel<<<1024, 256>>>();                                              // 2
    pre_T_kernel<<<1280, 256>>>(surf_interp, dir_interp);                             // 3
    pre_G_kernel<<<1280, 256>>>();                                                    // 4
    fr_kernel<<<NPATH / 4, 128>>>(path_dirs, surf_interp, dir_interp,
                                  fib_points, mask, delays);                          // 5
    gemm_scatter_kernel<<<dim3(4, 256, 1), 256, 2 * STAGE_ELEMS * 2>>>(delays);       // 6 (profiled)
    conv_kernel<<<dim3((RIRLEN + CT - 1) / CT, B_SZ), 256>>>(source_kernel, out);     // 7
}

// round 6
// speedup vs baseline: 1.4159x; 1.4159x over previous
#include <cuda_runtime.h>
#include <cuda_bf16.h>
#include <cuda_fp16.h>
#include <math.h>
#include <stdint.h>

// ---------------- problem constants ----------------
#define B_SZ 8
#define P_SZ 4096
#define NPATH (B_SZ * P_SZ)      // 32768
#define S_SZ 16
#define NFIB 128
#define NBAND 10
#define FLEN 1023
#define RIRLEN 96000
#define EPS 1e-9f
#define AMP_SCALE 1024.0f
#define INV_AMP_SCALE (1.0f / 1024.0f)

// ---------------- device scratch ----------------
__device__ float g_cosW[512 * 512];     // fp32 twiddles for phase precompute
__device__ float g_sinW[512 * 512];
__device__ float g_T[20 * 512];
__device__ float g_G[20 * 512];
__device__ float g_logrefl[S_SZ * NBAND];
__device__ float g_sigdir[NFIB * NBAND];
// fp16 GEMM operands
__device__ __half g_c16[512 * 512];     // cos
__device__ __half g_s16[512 * 512];     // sin
__device__ __half g_re16[NPATH * 512];  // scaled Re
__device__ __half g_im16[NPATH * 512];  // scaled -Im ... (stores +Im sign handled below)
__device__ float g_rir[B_SZ * RIRLEN];

// ---------------- launch 1: zero RIR + tiny param transforms ----------------
__global__ void init_kernel(const float* __restrict__ sp,
                            const float* __restrict__ dp) {
    int i = blockIdx.x * blockDim.x + threadIdx.x;
    if (i < B_SZ * RIRLEN) g_rir[i] = 0.f;
    if (i < S_SZ * NBAND) {
        float s = 1.f / (1.f + expf(-sp[i]));
        g_logrefl[i] = logf(s <= EPS ? EPS : s);
    }
    if (i < NFIB * NBAND) {
        g_sigdir[i] = 1.f / (1.f + expf(-dp[i]));
    }
}

// ---------------- launch 2: twiddles ----------------
__global__ void pre_twiddle_kernel() {
    int i = blockIdx.x * blockDim.x + threadIdx.x;
    if (i >= 512 * 512) return;
    int k = i >> 9, n = i & 511;
    int m = (k * n) % FLEN;                 // exact
    float x = (float)m * (2.0f / 1023.0f);  // in [0,2)
    float s, c;
    sincospif(x, &s, &c);
    g_cosW[i] = c;
    g_sinW[i] = s;
    g_c16[i] = __float2half_rn(c);
    g_s16[i] = __float2half_rn(s);
}

// ---------------- launch 3: T[j][n] ----------------
__global__ void pre_T_kernel(const float* __restrict__ si,
                             const float* __restrict__ di) {
    int gw = (blockIdx.x * 256 + threadIdx.x) >> 5;
    int lane = threadIdx.x & 31;
    if (gw >= 20 * 512) return;
    int j = gw >> 9, n = gw & 511;
    const float* row = (j < 10) ? (si + j * 512) : (di + (j - 10) * 512);
    float acc = 0.f;
    for (int k = 1 + lane; k < 512; k += 32)
        acc += row[k] * g_cosW[n * 512 + k];
    acc *= 2.f;
#pragma unroll
    for (int o = 16; o; o >>= 1) acc += __shfl_xor_sync(0xffffffffu, acc, o);
    if (lane == 0) g_T[gw] = acc + row[0];
}

// ---------------- launch 4: G[j][q] ----------------
__global__ void pre_G_kernel() {
    int gw = (blockIdx.x * 256 + threadIdx.x) >> 5;
    int lane = threadIdx.x & 31;
    if (gw >= 20 * 512) return;
    int j = gw >> 9, q = gw & 511;
    float acc = 0.f;
    for (int n = 1 + lane; n < 512; n += 32)
        acc += g_T[j * 512 + n] * g_sinW[q * 512 + n];
#pragma unroll
    for (int o = 16; o; o >>= 1) acc += __shfl_xor_sync(0xffffffffu, acc, o);
    if (lane == 0) g_G[gw] = acc * (-2.f / (float)FLEN);
}

// ---------------- launch 5: per-path spectrum (warp per path) ----------------
__global__ void __launch_bounds__(128) fr_kernel(
    const float* __restrict__ path_dirs,
    const float* __restrict__ surf_interp,
    const float* __restrict__ dir_interp,
    const float* __restrict__ fib,
    const int* __restrict__ mask,
    const int* __restrict__ delays) {
    int wid = threadIdx.x >> 5, lane = threadIdx.x & 31;
    int path = blockIdx.x * 4 + wid;

    __shared__ float sh_c[4][20];

    if (lane < NBAND) {
        const int* m = mask + path * S_SZ;
        float acc = 0.f;
#pragma unroll
        for (int s = 0; s < S_SZ; s++) acc += (float)m[s] * g_logrefl[s * NBAND + lane];
        sh_c[wid][lane] = acc;
    }

    float dx = path_dirs[path * 3 + 0];
    float dy = path_dirs[path * 3 + 1];
    float dz = path_dirs[path * 3 + 2];
    float inv = 1.f / (sqrtf(dx * dx + dy * dy + dz * dz) + EPS);
    dx *= inv; dy *= inv; dz *= inv;

    float lg[4];
    float mx = -1e30f;
#pragma unroll
    for (int j = 0; j < 4; j++) {
        int n = j * 32 + lane;
        lg[j] = 8.f * (dx * fib[n * 3 + 0] + dy * fib[n * 3 + 1] + dz * fib[n * 3 + 2]);
        mx = fmaxf(mx, lg[j]);
    }
#pragma unroll
    for (int o = 16; o; o >>= 1) mx = fmaxf(mx, __shfl_xor_sync(0xffffffffu, mx, o));
    float ev[4];
    float tot = 0.f;
#pragma unroll
    for (int j = 0; j < 4; j++) { ev[j] = __expf(lg[j] - mx); tot += ev[j]; }
#pragma unroll
    for (int o = 16; o; o >>= 1) tot += __shfl_xor_sync(0xffffffffu, tot, o);
    float itot = 1.f / tot;

#pragma unroll
    for (int band = 0; band < NBAND; band++) {
        float p = 0.f;
#pragma unroll
        for (int j = 0; j < 4; j++)
            p += ev[j] * g_sigdir[(j * 32 + lane) * NBAND + band];
#pragma unroll
        for (int o = 16; o; o >>= 1) p += __shfl_xor_sync(0xffffffffu, p, o);
        if (lane == 0) {
            float amp = p * itot;
            sh_c[wid][10 + band] = logf(amp <= EPS ? EPS : amp);
        }
    }
    __syncwarp();

    int dly = delays[path];
    float gain = 1.f / fmaxf((float)dly * (1.f / 48.f), 1.f);
    float base_scale = gain * (AMP_SCALE / (float)FLEN);

    float c[20];
#pragma unroll
    for (int j = 0; j < 20; j++) c[j] = sh_c[wid][j];

#pragma unroll 2
    for (int q = lane; q < 512; q += 32) {
        float la = 0.f, ph = 0.f;
#pragma unroll
        for (int j = 0; j < 10; j++) la += c[j] * surf_interp[j * 512 + q];
#pragma unroll
        for (int j = 0; j < 10; j++) la += c[10 + j] * dir_interp[j * 512 + q];
#pragma unroll
        for (int j = 0; j < 20; j++) ph += c[j] * g_G[j * 512 + q];
        float a = __expf(la) * base_scale * (q == 0 ? 1.f : 2.f);
        float kk = rintf(ph * 0.15915494309189535f);
        float phr = fmaf(-6.2831855f, kk, ph);
        phr = fmaf(1.7484555e-7f, kk, phr);
        float sn, cs;
        __sincosf(phr, &sn, &cs);
        size_t o = (size_t)path * 512 + q;
        g_re16[o] = __float2half_rn(a * cs);
        g_im16[o] = __float2half_rn(-a * sn);
    }
}

// ---------------- launch 6: fp16 tensor-core DFT + fused scatter ----------------
#define GST 24  // smem row stride in halfs (16 data + 8 pad)

#define LDSM4(r, addr)                                                      \
    asm volatile("ldmatrix.sync.aligned.m8n8.x4.shared.b16 {%0,%1,%2,%3}, [%4];" \
                 : "=r"((r)[0]), "=r"((r)[1]), "=r"((r)[2]), "=r"((r)[3])   \
                 : "r"(addr))

#define MMA_F16(acc, a, b0, b1)                                             \
    asm volatile("mma.sync.aligned.m16n8k16.row.col.f32.f16.f16.f32 "       \
                 "{%0,%1,%2,%3}, {%4,%5,%6,%7}, {%8,%9}, {%0,%1,%2,%3};"    \
                 : "+f"((acc)[0]), "+f"((acc)[1]), "+f"((acc)[2]), "+f"((acc)[3]) \
                 : "r"((a)[0]), "r"((a)[1]), "r"((a)[2]), "r"((a)[3]),      \
                   "r"(b0), "r"(b1))

__global__ void __launch_bounds__(256, 1) gemm_scatter_kernel(
    const int* __restrict__ delays) {
    __shared__ __half sm[4 * 128 * GST];  // tiles: 0 re, 1 im, 2 cos, 3 sin
    int tid = threadIdx.x;
    int wid = tid >> 5, lane = tid & 31;
    int wm = (wid & 3) * 32;
    int wn = (wid >> 2) * 64;
    int rowBase = blockIdx.y * 128;
    int colBase = blockIdx.x * 128;

    const __half* gsrc[4] = {g_re16, g_im16, g_c16, g_s16};
    int lr = tid >> 1;
    int lc = (tid & 1) * 8;

    float accC[2][8][4];
    float accS[2][8][4];
#pragma unroll
    for (int mt = 0; mt < 2; mt++)
#pragma unroll
        for (int nt = 0; nt < 8; nt++)
#pragma unroll
            for (int r = 0; r < 4; r++) { accC[mt][nt][r] = 0.f; accS[mt][nt][r] = 0.f; }

    unsigned smbase = (unsigned)__cvta_generic_to_shared(sm);
    int sel = lane >> 3, fr8 = lane & 7;
    int a_row_off = ((sel & 1) << 3) + fr8;
    int a_koff = (sel >> 1) << 3;
    int b_row_off = ((sel >> 1) << 3) + fr8;
    int b_koff = (sel & 1) << 3;

    uint4 ld[4];
#pragma unroll
    for (int t = 0; t < 4; t++) {
        int gr = (t < 2 ? rowBase : colBase) + lr;
        ld[t] = *(const uint4*)(gsrc[t] + (size_t)gr * 512 + lc);
    }

    for (int k0 = 0; k0 < 512; k0 += 16) {
#pragma unroll
        for (int t = 0; t < 4; t++)
            *(uint4*)((char*)sm + ((t * 128 + lr) * GST + lc) * 2) = ld[t];
        __syncthreads();
        if (k0 + 16 < 512) {
#pragma unroll
            for (int t = 0; t < 4; t++) {
                int gr = (t < 2 ? rowBase : colBase) + lr;
                ld[t] = *(const uint4*)(gsrc[t] + (size_t)gr * 512 + (k0 + 16) + lc);
            }
        }
        uint32_t af[2][2][4];
#pragma unroll
        for (int mat = 0; mat < 2; mat++)
#pragma unroll
            for (int mt = 0; mt < 2; mt++) {
                int row = wm + mt * 16 + a_row_off;
                unsigned addr = smbase + ((mat * 128 + row) * GST + a_koff) * 2;
                LDSM4(af[mat][mt], addr);
            }
#pragma unroll
        for (int g = 0; g < 4; g++) {
            uint32_t bf[2][4];
#pragma unroll
            for (int mat = 0; mat < 2; mat++) {
                int row = wn + g * 16 + b_row_off;
                unsigned addr = smbase + (((2 + mat) * 128 + row) * GST + b_koff) * 2;
                LDSM4(bf[mat], addr);
            }
#pragma unroll
            for (int mt = 0; mt < 2; mt++) {
#pragma unroll
                for (int j = 0; j < 2; j++) {
                    int nt = g * 2 + j;
                    MMA_F16(accC[mt][nt], af[0][mt], bf[0][2 * j], bf[0][2 * j + 1]); // re*cos
                    MMA_F16(accS[mt][nt], af[1][mt], bf[1][2 * j], bf[1][2 * j + 1]); // im*sin
                }
            }
        }
        __syncthreads();
    }

    // epilogue: unscale + scatter into RIR with atomics
    int r0 = lane >> 2, cp = (lane & 3) * 2;
#pragma unroll
    for (int mt = 0; mt < 2; mt++) {
#pragma unroll
        for (int half = 0; half < 2; half++) {
            int path = rowBase + wm + mt * 16 + half * 8 + r0;
            int dly = delays[path];
            float* rir = g_rir + (size_t)(path >> 12) * RIRLEN + dly;
#pragma unroll
            for (int nt = 0; nt < 8; nt++) {
                int n = colBase + wn + nt * 8 + cp;
                float c0 = accC[mt][nt][half * 2 + 0], s0 = accS[mt][nt][half * 2 + 0];
                float c1 = accC[mt][nt][half * 2 + 1], s1 = accS[mt][nt][half * 2 + 1];
                atomicAdd(rir + n, (c0 - s0) * INV_AMP_SCALE);
                atomicAdd(rir + n + 1, (c1 - s1) * INV_AMP_SCALE);
                if (n > 0) atomicAdd(rir + FLEN - n, (c0 + s0) * INV_AMP_SCALE);
                atomicAdd(rir + FLEN - (n + 1), (c1 + s1) * INV_AMP_SCALE);
            }
        }
    }
}

// ---------------- launch 7: 'same' cross-correlation ----------------
#define CT 1024
__global__ void __launch_bounds__(256) conv_kernel(const float* __restrict__ sk,
                                                   float* __restrict__ out) {
    __shared__ float s_rir[CT + 1024];
    __shared__ float s_k[1024];
    int b = blockIdx.y;
    int t0 = blockIdx.x * CT;
    int tid = threadIdx.x;

    for (int i = tid; i < CT + 1024; i += 256) {
        int idx = t0 - 511 + i;
        s_rir[i] = (idx >= 0 && idx < RIRLEN) ? g_rir[(size_t)b * RIRLEN + idx] : 0.f;
    }
    for (int i = tid; i < 1024; i += 256) s_k[i] = (i < FLEN) ? sk[i] : 0.f;
    __syncthreads();

    int base = tid * 4;
    float4 acc = make_float4(0.f, 0.f, 0.f, 0.f);
#pragma unroll 4
    for (int l = 0; l < 1024; l += 4) {
        float4 kv = *(const float4*)&s_k[l];
        float4 f0 = *(const float4*)&s_rir[base + l];
        float4 f1 = *(const float4*)&s_rir[base + l + 4];
        acc.x += kv.x * f0.x + kv.y * f0.y + kv.z * f0.z + kv.w * f0.w;
        acc.y += kv.x * f0.y + kv.y * f0.z + kv.z * f0.w + kv.w * f1.x;
        acc.z += kv.x * f0.z + kv.y * f0.w + kv.z * f1.x + kv.w * f1.y;
        acc.w += kv.x * f0.w + kv.y * f1.x + kv.z * f1.y + kv.w * f1.z;
    }
    int tbase = t0 + base;
    if (tbase + 0 < RIRLEN) out[(size_t)b * RIRLEN + tbase + 0] = acc.x;
    if (tbase + 1 < RIRLEN) out[(size_t)b * RIRLEN + tbase + 1] = acc.y;
    if (tbase + 2 < RIRLEN) out[(size_t)b * RIRLEN + tbase + 2] = acc.z;
    if (tbase + 3 < RIRLEN) out[(size_t)b * RIRLEN + tbase + 3] = acc.w;
}

// ---------------- launch ----------------
extern "C" void kernel_launch(void* const* d_in, const int* in_sizes, int n_in,
                              void* d_out, int out_size) {
    const float* surface_params = (const float*)d_in[0];
    const float* dir_params     = (const float*)d_in[1];
    const float* path_dirs      = (const float*)d_in[2];
    const float* source_kernel  = (const float*)d_in[3];
    const float* surf_interp    = (const float*)d_in[4];
    const float* dir_interp     = (const float*)d_in[5];
    const float* fib_points     = (const float*)d_in[6];
    const int*   mask           = (const int*)d_in[7];
    const int*   delays         = (const int*)d_in[8];
    float* out = (float*)d_out;

    init_kernel<<<(B_SZ * RIRLEN + 1023) / 1024, 1024>>>(surface_params, dir_params); // 1
    pre_twiddle_kernel<<<1024, 256>>>();                                              // 2
    pre_T_kernel<<<1280, 256>>>(surf_interp, dir_interp);                             // 3
    pre_G_kernel<<<1280, 256>>>();                                                    // 4
    fr_kernel<<<NPATH / 4, 128>>>(path_dirs, surf_interp, dir_interp,
                                  fib_points, mask, delays);                          // 5
    gemm_scatter_kernel<<<dim3(4, 256, 1), 256>>>(delays);                            // 6 (profiled)
    conv_kernel<<<dim3((RIRLEN + CT - 1) / CT, B_SZ), 256>>>(source_kernel, out);     // 7
}

// round 7
// speedup vs baseline: 1.4753x; 1.0419x over previous
#include <cuda_runtime.h>
#include <cuda_bf16.h>
#include <cuda_fp16.h>
#include <math.h>
#include <stdint.h>

// ---------------- problem constants ----------------
#define B_SZ 8
#define P_SZ 4096
#define NPATH (B_SZ * P_SZ)      // 32768
#define S_SZ 16
#define NFIB 128
#define NBAND 10
#define FLEN 1023
#define RIRLEN 96000
#define EPS 1e-9f
#define AMP_SCALE 1024.0f
#define INV_AMP_SCALE (1.0f / 1024.0f)

// ---------------- device scratch ----------------
__device__ float g_D[1024];             // Dirichlet half-sum table D(m), m in [0,1023)
__device__ float g_G[20 * 512];         // phase map: phase[q] = c . G[:,q]
__device__ float g_logrefl[S_SZ * NBAND];
__device__ float g_sigdir[NFIB * NBAND];
__device__ __half g_c16[512 * 512];     // cos twiddles
__device__ __half g_s16[512 * 512];     // sin twiddles
__device__ __half g_re16[NPATH * 512];  // scaled Re spectrum
__device__ __half g_im16[NPATH * 512];  // scaled -Im spectrum
__device__ float g_rir[B_SZ * RIRLEN];

// ---------------- launch 1: fused init (rir zero, params, D table, twiddles) ----
__global__ void init_kernel(const float* __restrict__ sp,
                            const float* __restrict__ dp) {
    int i = blockIdx.x * blockDim.x + threadIdx.x;
    if (i < B_SZ * RIRLEN) g_rir[i] = 0.f;
    if (i < S_SZ * NBAND) {
        float s = 1.f / (1.f + expf(-sp[i]));
        g_logrefl[i] = logf(s <= EPS ? EPS : s);
    }
    if (i < NFIB * NBAND) {
        g_sigdir[i] = 1.f / (1.f + expf(-dp[i]));
    }
    if (i < FLEN) {
        // D(m) = sum_{n=1}^{511} sin(2 pi m n / 1023)
        //      = (cos(pi m/N) - (-1)^m) / (2 sin(pi m/N)),  D(0) = 0
        if (i == 0) g_D[0] = 0.f;
        else {
            float s, c;
            sincospif((float)i * (1.0f / 1023.0f), &s, &c);
            float par = (i & 1) ? -1.f : 1.f;
            g_D[i] = (c - par) / (2.f * s);
        }
    }
    if (i < 512 * 512) {
        int k = i >> 9, n = i & 511;
        int m = (k * n) % FLEN;                 // exact
        float x = (float)m * (2.0f / 1023.0f);  // in [0,2)
        float s, c;
        sincospif(x, &s, &c);
        g_c16[i] = __float2half_rn(c);
        g_s16[i] = __float2half_rn(s);
    }
}

// ---------------- launch 2: G[j][q] from closed-form Dirichlet table ----------
// G[j][q] = -(2/N) * [ row[0]*D(q) + sum_{k=1}^{511} row[k]*(D(q+k)+D(q-k)) ]
__global__ void pre_G_kernel(const float* __restrict__ si,
                             const float* __restrict__ di) {
    int gw = (blockIdx.x * 256 + threadIdx.x) >> 5;
    int lane = threadIdx.x & 31;
    if (gw >= 20 * 512) return;
    int j = gw >> 9, q = gw & 511;
    const float* row = (j < 10) ? (si + j * 512) : (di + (j - 10) * 512);
    float acc = 0.f;
    for (int k = 1 + lane; k < 512; k += 32) {
        float w = g_D[q + k];
        int d = q - k;
        w += (d >= 0) ? g_D[d] : -g_D[-d];
        acc += row[k] * w;
    }
#pragma unroll
    for (int o = 16; o; o >>= 1) acc += __shfl_xor_sync(0xffffffffu, acc, o);
    if (lane == 0) g_G[gw] = (acc + row[0] * g_D[q]) * (-2.f / (float)FLEN);
}

// ---------------- launch 3: per-path spectrum (warp per path) ----------------
__global__ void __launch_bounds__(128) fr_kernel(
    const float* __restrict__ path_dirs,
    const float* __restrict__ surf_interp,
    const float* __restrict__ dir_interp,
    const float* __restrict__ fib,
    const int* __restrict__ mask,
    const int* __restrict__ delays) {
    int wid = threadIdx.x >> 5, lane = threadIdx.x & 31;
    int path = blockIdx.x * 4 + wid;

    __shared__ float sh_c[4][20];

    if (lane < NBAND) {
        const int* m = mask + path * S_SZ;
        float acc = 0.f;
#pragma unroll
        for (int s = 0; s < S_SZ; s++) acc += (float)m[s] * g_logrefl[s * NBAND + lane];
        sh_c[wid][lane] = acc;
    }

    float dx = path_dirs[path * 3 + 0];
    float dy = path_dirs[path * 3 + 1];
    float dz = path_dirs[path * 3 + 2];
    float inv = 1.f / (sqrtf(dx * dx + dy * dy + dz * dz) + EPS);
    dx *= inv; dy *= inv; dz *= inv;

    float lg[4];
    float mx = -1e30f;
#pragma unroll
    for (int j = 0; j < 4; j++) {
        int n = j * 32 + lane;
        lg[j] = 8.f * (dx * fib[n * 3 + 0] + dy * fib[n * 3 + 1] + dz * fib[n * 3 + 2]);
        mx = fmaxf(mx, lg[j]);
    }
#pragma unroll
    for (int o = 16; o; o >>= 1) mx = fmaxf(mx, __shfl_xor_sync(0xffffffffu, mx, o));
    float ev[4];
    float tot = 0.f;
#pragma unroll
    for (int j = 0; j < 4; j++) { ev[j] = __expf(lg[j] - mx); tot += ev[j]; }
#pragma unroll
    for (int o = 16; o; o >>= 1) tot += __shfl_xor_sync(0xffffffffu, tot, o);
    float itot = 1.f / tot;

#pragma unroll
    for (int band = 0; band < NBAND; band++) {
        float p = 0.f;
#pragma unroll
        for (int j = 0; j < 4; j++)
            p += ev[j] * g_sigdir[(j * 32 + lane) * NBAND + band];
#pragma unroll
        for (int o = 16; o; o >>= 1) p += __shfl_xor_sync(0xffffffffu, p, o);
        if (lane == 0) {
            float amp = p * itot;
            sh_c[wid][10 + band] = logf(amp <= EPS ? EPS : amp);
        }
    }
    __syncwarp();

    int dly = delays[path];
    float gain = 1.f / fmaxf((float)dly * (1.f / 48.f), 1.f);
    float base_scale = gain * (AMP_SCALE / (float)FLEN);

    float c[20];
#pragma unroll
    for (int j = 0; j < 20; j++) c[j] = sh_c[wid][j];

#pragma unroll 2
    for (int q = lane; q < 512; q += 32) {
        float la = 0.f, ph = 0.f;
#pragma unroll
        for (int j = 0; j < 10; j++) la += c[j] * surf_interp[j * 512 + q];
#pragma unroll
        for (int j = 0; j < 10; j++) la += c[10 + j] * dir_interp[j * 512 + q];
#pragma unroll
        for (int j = 0; j < 20; j++) ph += c[j] * g_G[j * 512 + q];
        float a = __expf(la) * base_scale * (q == 0 ? 1.f : 2.f);
        float kk = rintf(ph * 0.15915494309189535f);
        float phr = fmaf(-6.2831855f, kk, ph);
        phr = fmaf(1.7484555e-7f, kk, phr);
        float sn, cs;
        __sincosf(phr, &sn, &cs);
        size_t o = (size_t)path * 512 + q;
        g_re16[o] = __float2half_rn(a * cs);
        g_im16[o] = __float2half_rn(-a * sn);
    }
}

// ---------------- launch 4 (profiled): fp16 TC DFT + fused scatter ----------
#define GST 24  // smem row stride in halfs (16 data + 8 pad)

#define LDSM4(r, addr)                                                      \
    asm volatile("ldmatrix.sync.aligned.m8n8.x4.shared.b16 {%0,%1,%2,%3}, [%4];" \
                 : "=r"((r)[0]), "=r"((r)[1]), "=r"((r)[2]), "=r"((r)[3])   \
                 : "r"(addr))

#define MMA_F16(acc, a, b0, b1)                                             \
    asm volatile("mma.sync.aligned.m16n8k16.row.col.f32.f16.f16.f32 "       \
                 "{%0,%1,%2,%3}, {%4,%5,%6,%7}, {%8,%9}, {%0,%1,%2,%3};"    \
                 : "+f"((acc)[0]), "+f"((acc)[1]), "+f"((acc)[2]), "+f"((acc)[3]) \
                 : "r"((a)[0]), "r"((a)[1]), "r"((a)[2]), "r"((a)[3]),      \
                   "r"(b0), "r"(b1))

__global__ void __launch_bounds__(256, 1) gemm_scatter_kernel(
    const int* __restrict__ delays) {
    __shared__ __half sm[4 * 128 * GST];  // tiles: 0 re, 1 im, 2 cos, 3 sin
    int tid = threadIdx.x;
    int wid = tid >> 5, lane = tid & 31;
    int wm = (wid & 3) * 32;
    int wn = (wid >> 2) * 64;
    int rowBase = blockIdx.y * 128;
    int colBase = blockIdx.x * 128;

    const __half* gsrc[4] = {g_re16, g_im16, g_c16, g_s16};
    int lr = tid >> 1;
    int lc = (tid & 1) * 8;

    float accC[2][8][4];
    float accS[2][8][4];
#pragma unroll
    for (int mt = 0; mt < 2; mt++)
#pragma unroll
        for (int nt = 0; nt < 8; nt++)
#pragma unroll
            for (int r = 0; r < 4; r++) { accC[mt][nt][r] = 0.f; accS[mt][nt][r] = 0.f; }

    unsigned smbase = (unsigned)__cvta_generic_to_shared(sm);
    int sel = lane >> 3, fr8 = lane & 7;
    int a_row_off = ((sel & 1) << 3) + fr8;
    int a_koff = (sel >> 1) << 3;
    int b_row_off = ((sel >> 1) << 3) + fr8;
    int b_koff = (sel & 1) << 3;

    uint4 ld[4];
#pragma unroll
    for (int t = 0; t < 4; t++) {
        int gr = (t < 2 ? rowBase : colBase) + lr;
        ld[t] = *(const uint4*)(gsrc[t] + (size_t)gr * 512 + lc);
    }

    for (int k0 = 0; k0 < 512; k0 += 16) {
#pragma unroll
        for (int t = 0; t < 4; t++)
            *(uint4*)((char*)sm + ((t * 128 + lr) * GST + lc) * 2) = ld[t];
        __syncthreads();
        if (k0 + 16 < 512) {
#pragma unroll
            for (int t = 0; t < 4; t++) {
                int gr = (t < 2 ? rowBase : colBase) + lr;
                ld[t] = *(const uint4*)(gsrc[t] + (size_t)gr * 512 + (k0 + 16) + lc);
            }
        }
        uint32_t af[2][2][4];
#pragma unroll
        for (int mat = 0; mat < 2; mat++)
#pragma unroll
            for (int mt = 0; mt < 2; mt++) {
                int row = wm + mt * 16 + a_row_off;
                unsigned addr = smbase + ((mat * 128 + row) * GST + a_koff) * 2;
                LDSM4(af[mat][mt], addr);
            }
#pragma unroll
        for (int g = 0; g < 4; g++) {
            uint32_t bf[2][4];
#pragma unroll
            for (int mat = 0; mat < 2; mat++) {
                int row = wn + g * 16 + b_row_off;
                unsigned addr = smbase + (((2 + mat) * 128 + row) * GST + b_koff) * 2;
                LDSM4(bf[mat], addr);
            }
#pragma unroll
            for (int mt = 0; mt < 2; mt++) {
#pragma unroll
                for (int j = 0; j < 2; j++) {
                    int nt = g * 2 + j;
                    MMA_F16(accC[mt][nt], af[0][mt], bf[0][2 * j], bf[0][2 * j + 1]); // re*cos
                    MMA_F16(accS[mt][nt], af[1][mt], bf[1][2 * j], bf[1][2 * j + 1]); // im*sin
                }
            }
        }
        __syncthreads();
    }

    // epilogue: unscale + scatter into RIR with atomics
    int r0 = lane >> 2, cp = (lane & 3) * 2;
#pragma unroll
    for (int mt = 0; mt < 2; mt++) {
#pragma unroll
        for (int half = 0; half < 2; half++) {
            int path = rowBase + wm + mt * 16 + half * 8 + r0;
            int dly = delays[path];
            float* rir = g_rir + (size_t)(path >> 12) * RIRLEN + dly;
#pragma unroll
            for (int nt = 0; nt < 8; nt++) {
                int n = colBase + wn + nt * 8 + cp;
                float c0 = accC[mt][nt][half * 2 + 0], s0 = accS[mt][nt][half * 2 + 0];
                float c1 = accC[mt][nt][half * 2 + 1], s1 = accS[mt][nt][half * 2 + 1];
                atomicAdd(rir + n, (c0 - s0) * INV_AMP_SCALE);
                atomicAdd(rir + n + 1, (c1 - s1) * INV_AMP_SCALE);
                if (n > 0) atomicAdd(rir + FLEN - n, (c0 + s0) * INV_AMP_SCALE);
                atomicAdd(rir + FLEN - (n + 1), (c1 + s1) * INV_AMP_SCALE);
            }
        }
    }
}

// ---------------- launch 5: 'same' cross-correlation (sliding window) --------
#define CT 1024
__global__ void __launch_bounds__(256) conv_kernel(const float* __restrict__ sk,
                                                   float* __restrict__ out) {
    __shared__ float s_rir[CT + 1024];
    __shared__ float s_k[1024];
    int b = blockIdx.y;
    int t0 = blockIdx.x * CT;
    int tid = threadIdx.x;

    for (int i = tid; i < CT + 1024; i += 256) {
        int idx = t0 - 511 + i;
        s_rir[i] = (idx >= 0 && idx < RIRLEN) ? g_rir[(size_t)b * RIRLEN + idx] : 0.f;
    }
    for (int i = tid; i < 1024; i += 256) s_k[i] = (i < FLEN) ? sk[i] : 0.f;
    __syncthreads();

    int base = tid * 4;
    float4 acc = make_float4(0.f, 0.f, 0.f, 0.f);
    float4 f0 = *(const float4*)&s_rir[base];
#pragma unroll 8
    for (int l = 0; l < 1024; l += 4) {
        float4 kv = *(const float4*)&s_k[l];
        float4 f1 = *(const float4*)&s_rir[base + l + 4];
        acc.x += kv.x * f0.x + kv.y * f0.y + kv.z * f0.z + kv.w * f0.w;
        acc.y += kv.x * f0.y + kv.y * f0.z + kv.z * f0.w + kv.w * f1.x;
        acc.z += kv.x * f0.z + kv.y * f0.w + kv.z * f1.x + kv.w * f1.y;
        acc.w += kv.x * f0.w + kv.y * f1.x + kv.z * f1.y + kv.w * f1.z;
        f0 = f1;
    }
    int tbase = t0 + base;
    if (tbase + 0 < RIRLEN) out[(size_t)b * RIRLEN + tbase + 0] = acc.x;
    if (tbase + 1 < RIRLEN) out[(size_t)b * RIRLEN + tbase + 1] = acc.y;
    if (tbase + 2 < RIRLEN) out[(size_t)b * RIRLEN + tbase + 2] = acc.z;
    if (tbase + 3 < RIRLEN) out[(size_t)b * RIRLEN + tbase + 3] = acc.w;
}

// ---------------- launch ----------------
extern "C" void kernel_launch(void* const* d_in, const int* in_sizes, int n_in,
                              void* d_out, int out_size) {
    const float* surface_params = (const float*)d_in[0];
    const float* dir_params     = (const float*)d_in[1];
    const float* path_dirs      = (const float*)d_in[2];
    const float* source_kernel  = (const float*)d_in[3];
    const float* surf_interp    = (const float*)d_in[4];
    const float* dir_interp     = (const float*)d_in[5];
    const float* fib_points     = (const float*)d_in[6];
    const int*   mask           = (const int*)d_in[7];
    const int*   delays         = (const int*)d_in[8];
    float* out = (float*)d_out;

    init_kernel<<<750, 1024>>>(surface_params, dir_params);                           // 1
    pre_G_kernel<<<1280, 256>>>(surf_interp, dir_interp);                             // 2
    fr_kernel<<<NPATH / 4, 128>>>(path_dirs, surf_interp, dir_interp,
                                  fib_points, mask, delays);                          // 3
    gemm_scatter_kernel<<<dim3(4, 256, 1), 256>>>(delays);                            // 4 (profiled)
    conv_kernel<<<dim3((RIRLEN + CT - 1) / CT, B_SZ), 256>>>(source_kernel, out);     // 5
}

// round 8
// speedup vs baseline: 1.6884x; 1.1445x over previous
#include <cuda_runtime.h>
#include <cuda_bf16.h>
#include <cuda_fp16.h>
#include <math.h>
#include <stdint.h>

// ---------------- problem constants ----------------
#define B_SZ 8
#define P_SZ 4096
#define NPATH (B_SZ * P_SZ)      // 32768
#define S_SZ 16
#define NFIB 128
#define NBAND 10
#define FLEN 1023
#define RIRLEN 96000
#define EPS 1e-9f
#define AMP_SCALE 1024.0f
#define INV_AMP_SCALE (1.0f / 1024.0f)

// ---------------- device scratch ----------------
__device__ float g_D[1024];             // Dirichlet half-sum table
__device__ float g_G[20 * 512];         // phase map
__device__ float g_logrefl[S_SZ * NBAND];
__device__ float g_sigdir[NFIB * NBAND];
__device__ __half g_c16[512 * 512];     // cos twiddles
__device__ __half g_s16[512 * 512];     // sin twiddles
__device__ __half g_re16[NPATH * 512];  // scaled Re spectrum
__device__ __half g_im16[NPATH * 512];  // scaled -Im spectrum
__device__ float g_rir[B_SZ * RIRLEN];

// ---------------- launch 1: fused init ----------------
__global__ void init_kernel(const float* __restrict__ sp,
                            const float* __restrict__ dp) {
    int i = blockIdx.x * blockDim.x + threadIdx.x;
    if (i < B_SZ * RIRLEN) g_rir[i] = 0.f;
    if (i < S_SZ * NBAND) {
        float s = 1.f / (1.f + expf(-sp[i]));
        g_logrefl[i] = logf(s <= EPS ? EPS : s);
    }
    if (i < NFIB * NBAND) {
        g_sigdir[i] = 1.f / (1.f + expf(-dp[i]));
    }
    if (i < FLEN) {
        if (i == 0) g_D[0] = 0.f;
        else {
            float s, c;
            sincospif((float)i * (1.0f / 1023.0f), &s, &c);
            float par = (i & 1) ? -1.f : 1.f;
            g_D[i] = (c - par) / (2.f * s);
        }
    }
    if (i < 512 * 512) {
        int k = i >> 9, n = i & 511;
        int m = (k * n) % FLEN;                       // exact phase index
        float x = (float)m * (6.283185307179586f / 1023.0f);
        float s, c;
        __sincosf(x, &s, &c);                          // fp16 targets: approx ok
        g_c16[i] = __float2half_rn(c);
        g_s16[i] = __float2half_rn(s);
    }
}

// ---------------- launch 2: G[j][q] via Dirichlet table ----------
__global__ void pre_G_kernel(const float* __restrict__ si,
                             const float* __restrict__ di) {
    int gw = (blockIdx.x * 256 + threadIdx.x) >> 5;
    int lane = threadIdx.x & 31;
    if (gw >= 20 * 512) return;
    int j = gw >> 9, q = gw & 511;
    const float* row = (j < 10) ? (si + j * 512) : (di + (j - 10) * 512);
    float acc = 0.f;
    for (int k = 1 + lane; k < 512; k += 32) {
        float w = g_D[q + k];
        int d = q - k;
        w += (d >= 0) ? g_D[d] : -g_D[-d];
        acc += row[k] * w;
    }
#pragma unroll
    for (int o = 16; o; o >>= 1) acc += __shfl_xor_sync(0xffffffffu, acc, o);
    if (lane == 0) g_G[gw] = (acc + row[0] * g_D[q]) * (-2.f / (float)FLEN);
}

// ---------------- launch 3: per-path spectrum (warp per path) ----------------
__global__ void __launch_bounds__(128) fr_kernel(
    const float* __restrict__ path_dirs,
    const float* __restrict__ surf_interp,
    const float* __restrict__ dir_interp,
    const float* __restrict__ fib,
    const int* __restrict__ mask,
    const int* __restrict__ delays) {
    int wid = threadIdx.x >> 5, lane = threadIdx.x & 31;
    int path = blockIdx.x * 4 + wid;

    __shared__ float sh_c[4][20];

    if (lane < NBAND) {
        const int* m = mask + path * S_SZ;
        float acc = 0.f;
#pragma unroll
        for (int s = 0; s < S_SZ; s++) acc += (float)m[s] * g_logrefl[s * NBAND + lane];
        sh_c[wid][lane] = acc;
    }

    float dx = path_dirs[path * 3 + 0];
    float dy = path_dirs[path * 3 + 1];
    float dz = path_dirs[path * 3 + 2];
    float inv = 1.f / (sqrtf(dx * dx + dy * dy + dz * dz) + EPS);
    dx *= inv; dy *= inv; dz *= inv;

    float lg[4];
    float mx = -1e30f;
#pragma unroll
    for (int j = 0; j < 4; j++) {
        int n = j * 32 + lane;
        lg[j] = 8.f * (dx * fib[n * 3 + 0] + dy * fib[n * 3 + 1] + dz * fib[n * 3 + 2]);
        mx = fmaxf(mx, lg[j]);
    }
#pragma unroll
    for (int o = 16; o; o >>= 1) mx = fmaxf(mx, __shfl_xor_sync(0xffffffffu, mx, o));
    float ev[4];
    float tot = 0.f;
#pragma unroll
    for (int j = 0; j < 4; j++) { ev[j] = __expf(lg[j] - mx); tot += ev[j]; }
#pragma unroll
    for (int o = 16; o; o >>= 1) tot += __shfl_xor_sync(0xffffffffu, tot, o);
    float itot = 1.f / tot;

#pragma unroll
    for (int band = 0; band < NBAND; band++) {
        float p = 0.f;
#pragma unroll
        for (int j = 0; j < 4; j++)
            p += ev[j] * g_sigdir[(j * 32 + lane) * NBAND + band];
#pragma unroll
        for (int o = 16; o; o >>= 1) p += __shfl_xor_sync(0xffffffffu, p, o);
        if (lane == 0) {
            float amp = p * itot;
            sh_c[wid][10 + band] = logf(amp <= EPS ? EPS : amp);
        }
    }
    __syncwarp();

    int dly = delays[path];
    float gain = 1.f / fmaxf((float)dly * (1.f / 48.f), 1.f);
    float base_scale = gain * (AMP_SCALE / (float)FLEN);

    float c[20];
#pragma unroll
    for (int j = 0; j < 20; j++) c[j] = sh_c[wid][j];

#pragma unroll 2
    for (int q = lane; q < 512; q += 32) {
        float la = 0.f, ph = 0.f;
#pragma unroll
        for (int j = 0; j < 10; j++) la += c[j] * surf_interp[j * 512 + q];
#pragma unroll
        for (int j = 0; j < 10; j++) la += c[10 + j] * dir_interp[j * 512 + q];
#pragma unroll
        for (int j = 0; j < 20; j++) ph += c[j] * g_G[j * 512 + q];
        float a = __expf(la) * base_scale * (q == 0 ? 1.f : 2.f);
        float kk = rintf(ph * 0.15915494309189535f);
        float phr = fmaf(-6.2831855f, kk, ph);
        phr = fmaf(1.7484555e-7f, kk, phr);
        float sn, cs;
        __sincosf(phr, &sn, &cs);
        size_t o = (size_t)path * 512 + q;
        g_re16[o] = __float2half_rn(a * cs);
        g_im16[o] = __float2half_rn(-a * sn);
    }
}

// ---------------- launch 4 (profiled): fp16 TC DFT + fused scatter ----------
// 3-stage cp.async pipeline, k-step 32, one __syncthreads per iter.
#define ROWSTR 40                         // halfs per smem row (32 data + 8 pad)
#define TILE_HALFS (128 * ROWSTR)
#define STAGE_HALFS (4 * TILE_HALFS)      // tiles: re, im, cos, sin
#define NSTAGE 3
#define GEMM_SMEM (NSTAGE * STAGE_HALFS * 2)   // 122880 B

#define LDSM4(r, addr)                                                      \
    asm volatile("ldmatrix.sync.aligned.m8n8.x4.shared.b16 {%0,%1,%2,%3}, [%4];" \
                 : "=r"((r)[0]), "=r"((r)[1]), "=r"((r)[2]), "=r"((r)[3])   \
                 : "r"(addr))

#define MMA_F16(acc, a, b0, b1)                                             \
    asm volatile("mma.sync.aligned.m16n8k16.row.col.f32.f16.f16.f32 "       \
                 "{%0,%1,%2,%3}, {%4,%5,%6,%7}, {%8,%9}, {%0,%1,%2,%3};"    \
                 : "+f"((acc)[0]), "+f"((acc)[1]), "+f"((acc)[2]), "+f"((acc)[3]) \
                 : "r"((a)[0]), "r"((a)[1]), "r"((a)[2]), "r"((a)[3]),      \
                   "r"(b0), "r"(b1))

__device__ __forceinline__ void cp16(unsigned saddr, const void* gaddr) {
    asm volatile("cp.async.ca.shared.global [%0], [%1], 16;\n" :: "r"(saddr), "l"(gaddr));
}

extern __shared__ __align__(16) __half dsm[];

__global__ void __launch_bounds__(256, 1) gemm_scatter_kernel(
    const int* __restrict__ delays) {
    int tid = threadIdx.x;
    int wid = tid >> 5, lane = tid & 31;
    int wm = (wid & 3) * 32;
    int wn = (wid >> 2) * 64;
    int rowBase = blockIdx.y * 128;
    int colBase = blockIdx.x * 128;

    const __half* gsrc[4] = {g_re16, g_im16, g_c16, g_s16};

    float accC[2][8][4];
    float accS[2][8][4];
#pragma unroll
    for (int mt = 0; mt < 2; mt++)
#pragma unroll
        for (int nt = 0; nt < 8; nt++)
#pragma unroll
            for (int r = 0; r < 4; r++) { accC[mt][nt][r] = 0.f; accS[mt][nt][r] = 0.f; }

    unsigned smbase = (unsigned)__cvta_generic_to_shared(dsm);
    int sel = lane >> 3, fr8 = lane & 7;
    int a_row_off = ((sel & 1) << 3) + fr8;
    int a_koff = (sel >> 1) << 3;
    int b_row_off = ((sel >> 1) << 3) + fr8;
    int b_koff = (sel & 1) << 3;

    // cp.async mapping: tile = tid>>6, 64 threads cover 512 16B-segments, 8 each
    int ltile = tid >> 6;
    int lw = tid & 63;
    const __half* lsrc = gsrc[ltile];
    int lbase = (ltile < 2 ? rowBase : colBase);

    auto load_stage = [&](int stage, int k0) {
        unsigned sb = smbase + (unsigned)((stage * STAGE_HALFS + ltile * TILE_HALFS) * 2);
#pragma unroll
        for (int s8 = 0; s8 < 8; s8++) {
            int seg = lw + s8 * 64;          // 0..511
            int row = seg >> 2, c16i = seg & 3;
            cp16(sb + (unsigned)((row * ROWSTR + c16i * 8) * 2),
                 lsrc + (size_t)(lbase + row) * 512 + k0 + c16i * 8);
        }
    };

    load_stage(0, 0);  asm volatile("cp.async.commit_group;");
    load_stage(1, 32); asm volatile("cp.async.commit_group;");

    for (int it = 0; it < 16; it++) {
        if (it < 15) asm volatile("cp.async.wait_group 1;");
        else         asm volatile("cp.async.wait_group 0;");
        __syncthreads();

        unsigned sbase = smbase + (unsigned)((it % 3) * STAGE_HALFS * 2);
#pragma unroll
        for (int kk = 0; kk < 32; kk += 16) {
            uint32_t af[2][2][4];
#pragma unroll
            for (int mat = 0; mat < 2; mat++)
#pragma unroll
                for (int mt = 0; mt < 2; mt++) {
                    int row = wm + mt * 16 + a_row_off;
                    unsigned addr = sbase + (mat * TILE_HALFS + row * ROWSTR + kk + a_koff) * 2;
                    LDSM4(af[mat][mt], addr);
                }
#pragma unroll
            for (int g = 0; g < 4; g++) {
                uint32_t bf[2][4];
#pragma unroll
                for (int mat = 0; mat < 2; mat++) {
                    int row = wn + g * 16 + b_row_off;
                    unsigned addr = sbase + ((2 + mat) * TILE_HALFS + row * ROWSTR + kk + b_koff) * 2;
                    LDSM4(bf[mat], addr);
                }
#pragma unroll
                for (int mt = 0; mt < 2; mt++) {
#pragma unroll
                    for (int j = 0; j < 2; j++) {
                        int nt = g * 2 + j;
                        MMA_F16(accC[mt][nt], af[0][mt], bf[0][2 * j], bf[0][2 * j + 1]); // re*cos
                        MMA_F16(accS[mt][nt], af[1][mt], bf[1][2 * j], bf[1][2 * j + 1]); // im*sin
                    }
                }
            }
        }
        if (it + 2 < 16) {
            load_stage((it + 2) % 3, (it + 2) * 32);
            asm volatile("cp.async.commit_group;");
        }
    }

    // epilogue: unscale + scatter into RIR with atomics
    int r0 = lane >> 2, cp = (lane & 3) * 2;
#pragma unroll
    for (int mt = 0; mt < 2; mt++) {
#pragma unroll
        for (int half = 0; half < 2; half++) {
            int path = rowBase + wm + mt * 16 + half * 8 + r0;
            int dly = delays[path];
            float* rir = g_rir + (size_t)(path >> 12) * RIRLEN + dly;
#pragma unroll
            for (int nt = 0; nt < 8; nt++) {
                int n = colBase + wn + nt * 8 + cp;
                float c0 = accC[mt][nt][half * 2 + 0], s0 = accS[mt][nt][half * 2 + 0];
                float c1 = accC[mt][nt][half * 2 + 1], s1 = accS[mt][nt][half * 2 + 1];
                atomicAdd(rir + n, (c0 - s0) * INV_AMP_SCALE);
                atomicAdd(rir + n + 1, (c1 - s1) * INV_AMP_SCALE);
                if (n > 0) atomicAdd(rir + FLEN - n, (c0 + s0) * INV_AMP_SCALE);
                atomicAdd(rir + FLEN - (n + 1), (c1 + s1) * INV_AMP_SCALE);
            }
        }
    }
}

// ---------------- launch 5: 'same' cross-correlation ----------------
#define CT 1024
__global__ void __launch_bounds__(256) conv_kernel(const float* __restrict__ sk,
                                                   float* __restrict__ out) {
    __shared__ float s_rir[CT + 1024];
    __shared__ float s_k[1024];
    int b = blockIdx.y;
    int t0 = blockIdx.x * CT;
    int tid = threadIdx.x;

    for (int i = tid; i < CT + 1024; i += 256) {
        int idx = t0 - 511 + i;
        s_rir[i] = (idx >= 0 && idx < RIRLEN) ? g_rir[(size_t)b * RIRLEN + idx] : 0.f;
    }
    for (int i = tid; i < 1024; i += 256) s_k[i] = (i < FLEN) ? sk[i] : 0.f;
    __syncthreads();

    int base = tid * 4;
    float4 acc = make_float4(0.f, 0.f, 0.f, 0.f);
    float4 f0 = *(const float4*)&s_rir[base];
#pragma unroll 8
    for (int l = 0; l < 1024; l += 4) {
        float4 kv = *(const float4*)&s_k[l];
        float4 f1 = *(const float4*)&s_rir[base + l + 4];
        acc.x += kv.x * f0.x + kv.y * f0.y + kv.z * f0.z + kv.w * f0.w;
        acc.y += kv.x * f0.y + kv.y * f0.z + kv.z * f0.w + kv.w * f1.x;
        acc.z += kv.x * f0.z + kv.y * f0.w + kv.z * f1.x + kv.w * f1.y;
        acc.w += kv.x * f0.w + kv.y * f1.x + kv.z * f1.y + kv.w * f1.z;
        f0 = f1;
    }
    int tbase = t0 + base;
    if (tbase + 0 < RIRLEN) out[(size_t)b * RIRLEN + tbase + 0] = acc.x;
    if (tbase + 1 < RIRLEN) out[(size_t)b * RIRLEN + tbase + 1] = acc.y;
    if (tbase + 2 < RIRLEN) out[(size_t)b * RIRLEN + tbase + 2] = acc.z;
    if (tbase + 3 < RIRLEN) out[(size_t)b * RIRLEN + tbase + 3] = acc.w;
}

// ---------------- launch ----------------
extern "C" void kernel_launch(void* const* d_in, const int* in_sizes, int n_in,
                              void* d_out, int out_size) {
    const float* surface_params = (const float*)d_in[0];
    const float* dir_params     = (const float*)d_in[1];
    const float* path_dirs      = (const float*)d_in[2];
    const float* source_kernel  = (const float*)d_in[3];
    const float* surf_interp    = (const float*)d_in[4];
    const float* dir_interp     = (const float*)d_in[5];
    const float* fib_points     = (const float*)d_in[6];
    const int*   mask           = (const int*)d_in[7];
    const int*   delays         = (const int*)d_in[8];
    float* out = (float*)d_out;

    static int smem_set = 0;
    if (!smem_set) {
        cudaFuncSetAttribute(gemm_scatter_kernel,
                             cudaFuncAttributeMaxDynamicSharedMemorySize, GEMM_SMEM);
        smem_set = 1;
    }

    init_kernel<<<750, 1024>>>(surface_params, dir_params);                           // 1
    pre_G_kernel<<<1280, 256>>>(surf_interp, dir_interp);                             // 2
    fr_kernel<<<NPATH / 4, 128>>>(path_dirs, surf_interp, dir_interp,
                                  fib_points, mask, delays);                          // 3
    gemm_scatter_kernel<<<dim3(4, 256, 1), 256, GEMM_SMEM>>>(delays);                 // 4 (profiled)
    conv_kernel<<<dim3((RIRLEN + CT - 1) / CT, B_SZ), 256>>>(source_kernel, out);     // 5
}